// round 10
// baseline (speedup 1.0000x reference)
#include <cuda_runtime.h>
#include <math.h>

#define B_SZ    2
#define S_LEN   2048
#define D_MODEL 768
#define N_HEADS 12
#define D_K     64
#define M_ROWS  (B_SZ * S_LEN)   /* 4096 */

// Scratch (allocation-free rule: __device__ globals)
__device__ float g_Qp[M_ROWS * D_MODEL];
__device__ float g_Kp[M_ROWS * D_MODEL];
__device__ float g_Vp[M_ROWS * D_MODEL];
__device__ float g_Xa[M_ROWS * D_MODEL];

// ---------------------------------------------------------------------------
// Batched GEMM: C[m][n] = sum_k A[m][k] * W[n][k] + bias[n]  (x @ W.T + b)
// blockIdx.z selects the (A, W, bias, C) tuple -> Q/K/V projections fused
// into one launch for wave packing. 128x128 tile, BK=8, 256 threads,
// 8x8 micro-tile, double-buffered smem (1 sync per k-iter, prefetch overlap).
// ---------------------------------------------------------------------------
struct GemmArgs {
    const float* A[3];
    const float* W[3];
    const float* bias[3];
    float*       C[3];
};

__global__ __launch_bounds__(256) void gemm_bias_nt(GemmArgs args, int M, int N, int K)
{
    __shared__ float As[2][8][132];   // [buf][k][m]  (132*4=528B, 16B-aligned rows)
    __shared__ float Bs[2][8][132];   // [buf][k][n]

    const int z = blockIdx.z;
    const float* __restrict__ A    = args.A[z];
    const float* __restrict__ W    = args.W[z];
    const float* __restrict__ bias = args.bias[z];
    float* __restrict__       C    = args.C[z];

    const int tid = threadIdx.x;
    const int tx  = tid & 15;
    const int ty  = tid >> 4;
    const int m0  = blockIdx.y * 128;
    const int n0  = blockIdx.x * 128;

    const int lr = tid >> 1;            // 0..127 (tile row)
    const int lc = (tid & 1) * 4;       // 0 or 4 (k chunk)
    const float* Ag = A + (size_t)(m0 + lr) * K + lc;
    const float* Wg = W + (size_t)(n0 + lr) * K + lc;

    float acc[8][8];
    #pragma unroll
    for (int i = 0; i < 8; i++)
        #pragma unroll
        for (int j = 0; j < 8; j++) acc[i][j] = 0.f;

    auto compute = [&](int buf) {
        #pragma unroll
        for (int k = 0; k < 8; k++) {
            float4 a0 = *(const float4*)&As[buf][k][ty*4];
            float4 a1 = *(const float4*)&As[buf][k][64 + ty*4];
            float4 b0 = *(const float4*)&Bs[buf][k][tx*4];
            float4 b1 = *(const float4*)&Bs[buf][k][64 + tx*4];
            float ar[8] = {a0.x,a0.y,a0.z,a0.w,a1.x,a1.y,a1.z,a1.w};
            float br[8] = {b0.x,b0.y,b0.z,b0.w,b1.x,b1.y,b1.z,b1.w};
            #pragma unroll
            for (int i = 0; i < 8; i++)
                #pragma unroll
                for (int j = 0; j < 8; j++)
                    acc[i][j] = fmaf(ar[i], br[j], acc[i][j]);
        }
    };

    // prologue: fill buffer 0
    {
        float4 av = *(const float4*)Ag;
        float4 wv = *(const float4*)Wg;
        As[0][lc+0][lr] = av.x; As[0][lc+1][lr] = av.y; As[0][lc+2][lr] = av.z; As[0][lc+3][lr] = av.w;
        Bs[0][lc+0][lr] = wv.x; Bs[0][lc+1][lr] = wv.y; Bs[0][lc+2][lr] = wv.z; Bs[0][lc+3][lr] = wv.w;
    }
    __syncthreads();

    int cur = 0;
    for (int kk = 8; kk < K; kk += 8) {
        float4 av = *(const float4*)(Ag + kk);   // prefetch next
        float4 wv = *(const float4*)(Wg + kk);
        compute(cur);
        const int nxt = cur ^ 1;
        As[nxt][lc+0][lr] = av.x; As[nxt][lc+1][lr] = av.y; As[nxt][lc+2][lr] = av.z; As[nxt][lc+3][lr] = av.w;
        Bs[nxt][lc+0][lr] = wv.x; Bs[nxt][lc+1][lr] = wv.y; Bs[nxt][lc+2][lr] = wv.z; Bs[nxt][lc+3][lr] = wv.w;
        __syncthreads();
        cur = nxt;
    }
    compute(cur);

    float bn[8];
    #pragma unroll
    for (int j = 0; j < 4; j++) {
        bn[j]     = bias[n0 + tx*4 + j];
        bn[4 + j] = bias[n0 + 64 + tx*4 + j];
    }

    #pragma unroll
    for (int i = 0; i < 8; i++) {
        int m = m0 + ((i < 4) ? (ty*4 + i) : (64 + ty*4 + i - 4));
        float4 o0 = make_float4(acc[i][0]+bn[0], acc[i][1]+bn[1], acc[i][2]+bn[2], acc[i][3]+bn[3]);
        float4 o1 = make_float4(acc[i][4]+bn[4], acc[i][5]+bn[5], acc[i][6]+bn[6], acc[i][7]+bn[7]);
        *(float4*)&C[(size_t)m * N + n0 + tx*4]      = o0;
        *(float4*)&C[(size_t)m * N + n0 + 64 + tx*4] = o1;
    }
}

// ---------------------------------------------------------------------------
// Fused masked attention (flash-style, online softmax), fp32.
// Tile: 128 queries x 128 keys. 256 threads = 16(tx) x 16(ty).
// S-pass micro-tile: 8q x 8k per thread (1.0 B/FMA from smem).
// PV-pass: P staged row-major [q][k] (stride 132 floats = 528B, 16B-aligned),
//   stored with conflict-free STS.128, read as broadcast float4 + per-k Vs
//   float4 -> 12 LDS per 128 FMA (FMA-bound).
// Grid: (S/128, H, B). Smem ~166KB -> 1 block/SM.
// ---------------------------------------------------------------------------
__global__ __launch_bounds__(256, 1) void attn_kernel(
    const float* __restrict__ Qp, const float* __restrict__ Kp,
    const float* __restrict__ Vp, const int* __restrict__ mask,
    float* __restrict__ X)
{
    extern __shared__ float sm[];
    float (*Qt)[132] = (float(*)[132])(sm);                          // [d][q]  64x132
    float (*Kt)[132] = (float(*)[132])(sm + 64*132);                 // [d][k]  64x132
    float (*Vs)[68]  = (float(*)[68]) (sm + 2*64*132);               // [k][d] 128x68
    float (*Ps)[132] = (float(*)[132])(sm + 2*64*132 + 128*68);      // [q][k] 128x132

    const int tid = threadIdx.x;
    const int tx  = tid & 15;
    const int ty  = tid >> 4;
    const int b   = blockIdx.z;
    const int h   = blockIdx.y;
    const int q0  = blockIdx.x * 128;

    const size_t rowbase  = (size_t)b * S_LEN;
    const int    hoff     = h * D_K;
    const size_t maskbase = (size_t)b * S_LEN * S_LEN;

    // loader mapping: row lr in tile, 32-col chunk cb; 32 consecutive lr per
    // warp -> transposed scalar stores hit all 32 banks (conflict-free)
    const int lr = tid & 127;
    const int cb = (tid >> 7) * 32;

    // Load Q tile (128 x 64) -> Qt[d][q]
    {
        const float* src = Qp + (rowbase + q0 + lr) * D_MODEL + hoff + cb;
        #pragma unroll
        for (int j = 0; j < 8; j++) {
            float4 v = *(const float4*)(src + j*4);
            Qt[cb + j*4 + 0][lr] = v.x;
            Qt[cb + j*4 + 1][lr] = v.y;
            Qt[cb + j*4 + 2][lr] = v.z;
            Qt[cb + j*4 + 3][lr] = v.w;
        }
    }

    float m_i[8], l_i[8], o[8][4];
    #pragma unroll
    for (int i = 0; i < 8; i++) {
        m_i[i] = -1e30f; l_i[i] = 0.f;
        #pragma unroll
        for (int j = 0; j < 4; j++) o[i][j] = 0.f;
    }

    for (int kt = 0; kt < S_LEN / 128; kt++) {
        const int k0 = kt * 128;
        __syncthreads();   // previous Ps/Vs reads complete before overwrite
        {
            const float* ks   = Kp + (rowbase + k0 + lr) * D_MODEL + hoff + cb;
            const float* vsrc = Vp + (rowbase + k0 + lr) * D_MODEL + hoff + cb;
            #pragma unroll
            for (int j = 0; j < 8; j++) {
                float4 kv = *(const float4*)(ks + j*4);
                Kt[cb + j*4 + 0][lr] = kv.x;
                Kt[cb + j*4 + 1][lr] = kv.y;
                Kt[cb + j*4 + 2][lr] = kv.z;
                Kt[cb + j*4 + 3][lr] = kv.w;
                *(float4*)&Vs[lr][cb + j*4] = *(const float4*)(vsrc + j*4);
            }
        }
        __syncthreads();

        // S = Q K^T  (8x8 per thread)
        float s[8][8];
        #pragma unroll
        for (int i = 0; i < 8; i++)
            #pragma unroll
            for (int j = 0; j < 8; j++) s[i][j] = 0.f;

        #pragma unroll 4
        for (int d = 0; d < 64; d++) {
            float4 qa0 = *(const float4*)&Qt[d][ty*4];
            float4 qa1 = *(const float4*)&Qt[d][64 + ty*4];
            float4 kb0 = *(const float4*)&Kt[d][tx*4];
            float4 kb1 = *(const float4*)&Kt[d][64 + tx*4];
            float ar[8] = {qa0.x,qa0.y,qa0.z,qa0.w,qa1.x,qa1.y,qa1.z,qa1.w};
            float br[8] = {kb0.x,kb0.y,kb0.z,kb0.w,kb1.x,kb1.y,kb1.z,kb1.w};
            #pragma unroll
            for (int i = 0; i < 8; i++)
                #pragma unroll
                for (int j = 0; j < 8; j++)
                    s[i][j] = fmaf(ar[i], br[j], s[i][j]);
        }

        // mask + scale + online softmax (row stats across the 16 tx lanes)
        #pragma unroll
        for (int i = 0; i < 8; i++) {
            const int qr = (i < 4) ? (ty*4 + i) : (64 + ty*4 + i - 4);
            const int* mrow = mask + maskbase + (size_t)(q0 + qr) * S_LEN + k0;
            const int4 mv0 = *(const int4*)(mrow + tx*4);
            const int4 mv1 = *(const int4*)(mrow + 64 + tx*4);
            float sv[8];
            sv[0] = (mv0.x != 0) ? s[i][0] * 0.125f : -1e9f;
            sv[1] = (mv0.y != 0) ? s[i][1] * 0.125f : -1e9f;
            sv[2] = (mv0.z != 0) ? s[i][2] * 0.125f : -1e9f;
            sv[3] = (mv0.w != 0) ? s[i][3] * 0.125f : -1e9f;
            sv[4] = (mv1.x != 0) ? s[i][4] * 0.125f : -1e9f;
            sv[5] = (mv1.y != 0) ? s[i][5] * 0.125f : -1e9f;
            sv[6] = (mv1.z != 0) ? s[i][6] * 0.125f : -1e9f;
            sv[7] = (mv1.w != 0) ? s[i][7] * 0.125f : -1e9f;

            float mt = sv[0];
            #pragma unroll
            for (int j = 1; j < 8; j++) mt = fmaxf(mt, sv[j]);
            #pragma unroll
            for (int w = 8; w >= 1; w >>= 1)
                mt = fmaxf(mt, __shfl_xor_sync(0xffffffffu, mt, w, 16));

            const float mn = fmaxf(m_i[i], mt);
            float rs = 0.f;
            #pragma unroll
            for (int j = 0; j < 8; j++) {
                float p = __expf(sv[j] - mn);
                s[i][j] = p;
                rs += p;
            }
            #pragma unroll
            for (int w = 8; w >= 1; w >>= 1)
                rs += __shfl_xor_sync(0xffffffffu, rs, w, 16);

            const float sc = __expf(m_i[i] - mn);
            l_i[i] = l_i[i] * sc + rs;
            m_i[i] = mn;
            #pragma unroll
            for (int j = 0; j < 4; j++) o[i][j] *= sc;
        }

        // Stage P row-major: Ps[q][k] via STS.128 (conflict-free)
        #pragma unroll
        for (int i = 0; i < 8; i++) {
            const int qr = (i < 4) ? (ty*4 + i) : (64 + ty*4 + i - 4);
            *(float4*)&Ps[qr][tx*4]      = make_float4(s[i][0], s[i][1], s[i][2], s[i][3]);
            *(float4*)&Ps[qr][64 + tx*4] = make_float4(s[i][4], s[i][5], s[i][6], s[i][7]);
        }
        __syncthreads();

        // O += P V  (8q x 4d per thread; k in chunks of 4)
        #pragma unroll 2
        for (int kk = 0; kk < 128; kk += 4) {
            float4 p[8];
            #pragma unroll
            for (int i = 0; i < 8; i++) {
                const int qr = (i < 4) ? (ty*4 + i) : (64 + ty*4 + i - 4);
                p[i] = *(const float4*)&Ps[qr][kk];   // broadcast within warp
            }
            #pragma unroll
            for (int t = 0; t < 4; t++) {
                float4 vb = *(const float4*)&Vs[kk + t][tx*4];
                #pragma unroll
                for (int i = 0; i < 8; i++) {
                    const float pi = (t == 0) ? p[i].x : (t == 1) ? p[i].y
                                   : (t == 2) ? p[i].z : p[i].w;
                    o[i][0] = fmaf(pi, vb.x, o[i][0]);
                    o[i][1] = fmaf(pi, vb.y, o[i][1]);
                    o[i][2] = fmaf(pi, vb.z, o[i][2]);
                    o[i][3] = fmaf(pi, vb.w, o[i][3]);
                }
            }
        }
    }

    // Epilogue: X[b, q, h*64 + d] = O / l
    #pragma unroll
    for (int i = 0; i < 8; i++) {
        const int qr = (i < 4) ? (ty*4 + i) : (64 + ty*4 + i - 4);
        const float inv = 1.0f / l_i[i];
        float4 outv = make_float4(o[i][0]*inv, o[i][1]*inv, o[i][2]*inv, o[i][3]*inv);
        *(float4*)&X[(rowbase + q0 + qr) * D_MODEL + hoff + tx*4] = outv;
    }
}

// ---------------------------------------------------------------------------
extern "C" void kernel_launch(void* const* d_in, const int* in_sizes, int n_in,
                              void* d_out, int out_size)
{
    const float* q    = (const float*)d_in[0];
    const float* k    = (const float*)d_in[1];
    const float* v    = (const float*)d_in[2];
    const int*   mask = (const int*)  d_in[3];
    const float* Wq   = (const float*)d_in[4];
    const float* bq   = (const float*)d_in[5];
    const float* Wk   = (const float*)d_in[6];
    const float* bk   = (const float*)d_in[7];
    const float* Wv   = (const float*)d_in[8];
    const float* bv   = (const float*)d_in[9];
    const float* Wo   = (const float*)d_in[10];
    const float* bo   = (const float*)d_in[11];
    float* out = (float*)d_out;

    float *Qp, *Kp, *Vp, *Xa;
    cudaGetSymbolAddress((void**)&Qp, g_Qp);
    cudaGetSymbolAddress((void**)&Kp, g_Kp);
    cudaGetSymbolAddress((void**)&Vp, g_Vp);
    cudaGetSymbolAddress((void**)&Xa, g_Xa);

    const int attn_smem = (2*64*132 + 128*68 + 128*132) * (int)sizeof(float); // 169984 B
    cudaFuncSetAttribute(attn_kernel, cudaFuncAttributeMaxDynamicSharedMemorySize, attn_smem);

    dim3 gblk(256);

    // Fused Q/K/V projections: one launch, 576 blocks (better wave packing)
    GemmArgs qkv;
    qkv.A[0] = q;  qkv.A[1] = k;  qkv.A[2] = v;
    qkv.W[0] = Wq; qkv.W[1] = Wk; qkv.W[2] = Wv;
    qkv.bias[0] = bq; qkv.bias[1] = bk; qkv.bias[2] = bv;
    qkv.C[0] = Qp; qkv.C[1] = Kp; qkv.C[2] = Vp;
    gemm_bias_nt<<<dim3(D_MODEL/128, M_ROWS/128, 3), gblk>>>(qkv, M_ROWS, D_MODEL, D_MODEL);

    attn_kernel<<<dim3(S_LEN/128, N_HEADS, B_SZ), 256, attn_smem>>>(Qp, Kp, Vp, mask, Xa);

    // Output projection
    GemmArgs og;
    og.A[0] = Xa; og.A[1] = Xa; og.A[2] = Xa;
    og.W[0] = Wo; og.W[1] = Wo; og.W[2] = Wo;
    og.bias[0] = bo; og.bias[1] = bo; og.bias[2] = bo;
    og.C[0] = out; og.C[1] = out; og.C[2] = out;
    gemm_bias_nt<<<dim3(D_MODEL/128, M_ROWS/128, 1), gblk>>>(og, M_ROWS, D_MODEL, D_MODEL);
}

// round 11
// speedup vs baseline: 1.0006x; 1.0006x over previous
#include <cuda_runtime.h>
#include <math.h>

#define B_SZ    2
#define S_LEN   2048
#define D_MODEL 768
#define N_HEADS 12
#define D_K     64
#define M_ROWS  (B_SZ * S_LEN)   /* 4096 */

// Scratch (allocation-free rule: __device__ globals)
__device__ float g_Qp[M_ROWS * D_MODEL];
__device__ float g_Kp[M_ROWS * D_MODEL];
__device__ float g_Vp[M_ROWS * D_MODEL];
__device__ float g_Xa[M_ROWS * D_MODEL];

// ---------------------------------------------------------------------------
// Batched GEMM: C[m][n] = sum_k A[m][k] * W[n][k] + bias[n]  (x @ W.T + b)
// blockIdx.z selects the (A, W, bias, C) tuple -> Q/K/V projections fused
// into one launch for wave packing. 128x128 tile, BK=8, 256 threads,
// 8x8 micro-tile, double-buffered smem (1 sync per k-iter, prefetch overlap).
// ---------------------------------------------------------------------------
struct GemmArgs {
    const float* A[3];
    const float* W[3];
    const float* bias[3];
    float*       C[3];
};

__global__ __launch_bounds__(256) void gemm_bias_nt(GemmArgs args, int M, int N, int K)
{
    __shared__ float As[2][8][132];   // [buf][k][m]  (132*4=528B, 16B-aligned rows)
    __shared__ float Bs[2][8][132];   // [buf][k][n]

    const int z = blockIdx.z;
    const float* __restrict__ A    = args.A[z];
    const float* __restrict__ W    = args.W[z];
    const float* __restrict__ bias = args.bias[z];
    float* __restrict__       C    = args.C[z];

    const int tid = threadIdx.x;
    const int tx  = tid & 15;
    const int ty  = tid >> 4;
    const int m0  = blockIdx.y * 128;
    const int n0  = blockIdx.x * 128;

    const int lr = tid >> 1;            // 0..127 (tile row)
    const int lc = (tid & 1) * 4;       // 0 or 4 (k chunk)
    const float* Ag = A + (size_t)(m0 + lr) * K + lc;
    const float* Wg = W + (size_t)(n0 + lr) * K + lc;

    float acc[8][8];
    #pragma unroll
    for (int i = 0; i < 8; i++)
        #pragma unroll
        for (int j = 0; j < 8; j++) acc[i][j] = 0.f;

    auto compute = [&](int buf) {
        #pragma unroll
        for (int k = 0; k < 8; k++) {
            float4 a0 = *(const float4*)&As[buf][k][ty*4];
            float4 a1 = *(const float4*)&As[buf][k][64 + ty*4];
            float4 b0 = *(const float4*)&Bs[buf][k][tx*4];
            float4 b1 = *(const float4*)&Bs[buf][k][64 + tx*4];
            float ar[8] = {a0.x,a0.y,a0.z,a0.w,a1.x,a1.y,a1.z,a1.w};
            float br[8] = {b0.x,b0.y,b0.z,b0.w,b1.x,b1.y,b1.z,b1.w};
            #pragma unroll
            for (int i = 0; i < 8; i++)
                #pragma unroll
                for (int j = 0; j < 8; j++)
                    acc[i][j] = fmaf(ar[i], br[j], acc[i][j]);
        }
    };

    // prologue: fill buffer 0
    {
        float4 av = *(const float4*)Ag;
        float4 wv = *(const float4*)Wg;
        As[0][lc+0][lr] = av.x; As[0][lc+1][lr] = av.y; As[0][lc+2][lr] = av.z; As[0][lc+3][lr] = av.w;
        Bs[0][lc+0][lr] = wv.x; Bs[0][lc+1][lr] = wv.y; Bs[0][lc+2][lr] = wv.z; Bs[0][lc+3][lr] = wv.w;
    }
    __syncthreads();

    int cur = 0;
    for (int kk = 8; kk < K; kk += 8) {
        float4 av = *(const float4*)(Ag + kk);   // prefetch next
        float4 wv = *(const float4*)(Wg + kk);
        compute(cur);
        const int nxt = cur ^ 1;
        As[nxt][lc+0][lr] = av.x; As[nxt][lc+1][lr] = av.y; As[nxt][lc+2][lr] = av.z; As[nxt][lc+3][lr] = av.w;
        Bs[nxt][lc+0][lr] = wv.x; Bs[nxt][lc+1][lr] = wv.y; Bs[nxt][lc+2][lr] = wv.z; Bs[nxt][lc+3][lr] = wv.w;
        __syncthreads();
        cur = nxt;
    }
    compute(cur);

    float bn[8];
    #pragma unroll
    for (int j = 0; j < 4; j++) {
        bn[j]     = bias[n0 + tx*4 + j];
        bn[4 + j] = bias[n0 + 64 + tx*4 + j];
    }

    #pragma unroll
    for (int i = 0; i < 8; i++) {
        int m = m0 + ((i < 4) ? (ty*4 + i) : (64 + ty*4 + i - 4));
        float4 o0 = make_float4(acc[i][0]+bn[0], acc[i][1]+bn[1], acc[i][2]+bn[2], acc[i][3]+bn[3]);
        float4 o1 = make_float4(acc[i][4]+bn[4], acc[i][5]+bn[5], acc[i][6]+bn[6], acc[i][7]+bn[7]);
        *(float4*)&C[(size_t)m * N + n0 + tx*4]      = o0;
        *(float4*)&C[(size_t)m * N + n0 + 64 + tx*4] = o1;
    }
}

// ---------------------------------------------------------------------------
// Fused masked attention (flash-style, online softmax), fp32.
// Tile: 128 queries x 128 keys. 256 threads = 16(tx) x 16(ty).
// S-pass micro-tile: 8q x 8k per thread (1.0 B/FMA from smem).
// PV-pass: P staged row-major [q][k] (stride 132 floats = 528B, 16B-aligned),
//   stored with conflict-free STS.128, read as broadcast float4 + per-k Vs
//   float4 -> 12 LDS per 128 FMA (FMA-bound).
// Grid: (S/128, H, B). Smem ~166KB -> 1 block/SM.
// ---------------------------------------------------------------------------
__global__ __launch_bounds__(256, 1) void attn_kernel(
    const float* __restrict__ Qp, const float* __restrict__ Kp,
    const float* __restrict__ Vp, const int* __restrict__ mask,
    float* __restrict__ X)
{
    extern __shared__ float sm[];
    float (*Qt)[132] = (float(*)[132])(sm);                          // [d][q]  64x132
    float (*Kt)[132] = (float(*)[132])(sm + 64*132);                 // [d][k]  64x132
    float (*Vs)[68]  = (float(*)[68]) (sm + 2*64*132);               // [k][d] 128x68
    float (*Ps)[132] = (float(*)[132])(sm + 2*64*132 + 128*68);      // [q][k] 128x132

    const int tid = threadIdx.x;
    const int tx  = tid & 15;
    const int ty  = tid >> 4;
    const int b   = blockIdx.z;
    const int h   = blockIdx.y;
    const int q0  = blockIdx.x * 128;

    const size_t rowbase  = (size_t)b * S_LEN;
    const int    hoff     = h * D_K;
    const size_t maskbase = (size_t)b * S_LEN * S_LEN;

    // loader mapping: row lr in tile, 32-col chunk cb; 32 consecutive lr per
    // warp -> transposed scalar stores hit all 32 banks (conflict-free)
    const int lr = tid & 127;
    const int cb = (tid >> 7) * 32;

    // Load Q tile (128 x 64) -> Qt[d][q]
    {
        const float* src = Qp + (rowbase + q0 + lr) * D_MODEL + hoff + cb;
        #pragma unroll
        for (int j = 0; j < 8; j++) {
            float4 v = *(const float4*)(src + j*4);
            Qt[cb + j*4 + 0][lr] = v.x;
            Qt[cb + j*4 + 1][lr] = v.y;
            Qt[cb + j*4 + 2][lr] = v.z;
            Qt[cb + j*4 + 3][lr] = v.w;
        }
    }

    float m_i[8], l_i[8], o[8][4];
    #pragma unroll
    for (int i = 0; i < 8; i++) {
        m_i[i] = -1e30f; l_i[i] = 0.f;
        #pragma unroll
        for (int j = 0; j < 4; j++) o[i][j] = 0.f;
    }

    for (int kt = 0; kt < S_LEN / 128; kt++) {
        const int k0 = kt * 128;
        __syncthreads();   // previous Ps/Vs reads complete before overwrite
        {
            const float* ks   = Kp + (rowbase + k0 + lr) * D_MODEL + hoff + cb;
            const float* vsrc = Vp + (rowbase + k0 + lr) * D_MODEL + hoff + cb;
            #pragma unroll
            for (int j = 0; j < 8; j++) {
                float4 kv = *(const float4*)(ks + j*4);
                Kt[cb + j*4 + 0][lr] = kv.x;
                Kt[cb + j*4 + 1][lr] = kv.y;
                Kt[cb + j*4 + 2][lr] = kv.z;
                Kt[cb + j*4 + 3][lr] = kv.w;
                *(float4*)&Vs[lr][cb + j*4] = *(const float4*)(vsrc + j*4);
            }
        }
        __syncthreads();

        // S = Q K^T  (8x8 per thread)
        float s[8][8];
        #pragma unroll
        for (int i = 0; i < 8; i++)
            #pragma unroll
            for (int j = 0; j < 8; j++) s[i][j] = 0.f;

        #pragma unroll 4
        for (int d = 0; d < 64; d++) {
            float4 qa0 = *(const float4*)&Qt[d][ty*4];
            float4 qa1 = *(const float4*)&Qt[d][64 + ty*4];
            float4 kb0 = *(const float4*)&Kt[d][tx*4];
            float4 kb1 = *(const float4*)&Kt[d][64 + tx*4];
            float ar[8] = {qa0.x,qa0.y,qa0.z,qa0.w,qa1.x,qa1.y,qa1.z,qa1.w};
            float br[8] = {kb0.x,kb0.y,kb0.z,kb0.w,kb1.x,kb1.y,kb1.z,kb1.w};
            #pragma unroll
            for (int i = 0; i < 8; i++)
                #pragma unroll
                for (int j = 0; j < 8; j++)
                    s[i][j] = fmaf(ar[i], br[j], s[i][j]);
        }

        // mask + scale + online softmax (row stats across the 16 tx lanes)
        #pragma unroll
        for (int i = 0; i < 8; i++) {
            const int qr = (i < 4) ? (ty*4 + i) : (64 + ty*4 + i - 4);
            const int* mrow = mask + maskbase + (size_t)(q0 + qr) * S_LEN + k0;
            const int4 mv0 = *(const int4*)(mrow + tx*4);
            const int4 mv1 = *(const int4*)(mrow + 64 + tx*4);
            float sv[8];
            sv[0] = (mv0.x != 0) ? s[i][0] * 0.125f : -1e9f;
            sv[1] = (mv0.y != 0) ? s[i][1] * 0.125f : -1e9f;
            sv[2] = (mv0.z != 0) ? s[i][2] * 0.125f : -1e9f;
            sv[3] = (mv0.w != 0) ? s[i][3] * 0.125f : -1e9f;
            sv[4] = (mv1.x != 0) ? s[i][4] * 0.125f : -1e9f;
            sv[5] = (mv1.y != 0) ? s[i][5] * 0.125f : -1e9f;
            sv[6] = (mv1.z != 0) ? s[i][6] * 0.125f : -1e9f;
            sv[7] = (mv1.w != 0) ? s[i][7] * 0.125f : -1e9f;

            float mt = sv[0];
            #pragma unroll
            for (int j = 1; j < 8; j++) mt = fmaxf(mt, sv[j]);
            #pragma unroll
            for (int w = 8; w >= 1; w >>= 1)
                mt = fmaxf(mt, __shfl_xor_sync(0xffffffffu, mt, w, 16));

            const float mn = fmaxf(m_i[i], mt);
            float rs = 0.f;
            #pragma unroll
            for (int j = 0; j < 8; j++) {
                float p = __expf(sv[j] - mn);
                s[i][j] = p;
                rs += p;
            }
            #pragma unroll
            for (int w = 8; w >= 1; w >>= 1)
                rs += __shfl_xor_sync(0xffffffffu, rs, w, 16);

            const float sc = __expf(m_i[i] - mn);
            l_i[i] = l_i[i] * sc + rs;
            m_i[i] = mn;
            #pragma unroll
            for (int j = 0; j < 4; j++) o[i][j] *= sc;
        }

        // Stage P row-major: Ps[q][k] via STS.128 (conflict-free)
        #pragma unroll
        for (int i = 0; i < 8; i++) {
            const int qr = (i < 4) ? (ty*4 + i) : (64 + ty*4 + i - 4);
            *(float4*)&Ps[qr][tx*4]      = make_float4(s[i][0], s[i][1], s[i][2], s[i][3]);
            *(float4*)&Ps[qr][64 + tx*4] = make_float4(s[i][4], s[i][5], s[i][6], s[i][7]);
        }
        __syncthreads();

        // O += P V  (8q x 4d per thread; k in chunks of 4)
        #pragma unroll 2
        for (int kk = 0; kk < 128; kk += 4) {
            float4 p[8];
            #pragma unroll
            for (int i = 0; i < 8; i++) {
                const int qr = (i < 4) ? (ty*4 + i) : (64 + ty*4 + i - 4);
                p[i] = *(const float4*)&Ps[qr][kk];   // broadcast within warp
            }
            #pragma unroll
            for (int t = 0; t < 4; t++) {
                float4 vb = *(const float4*)&Vs[kk + t][tx*4];
                #pragma unroll
                for (int i = 0; i < 8; i++) {
                    const float pi = (t == 0) ? p[i].x : (t == 1) ? p[i].y
                                   : (t == 2) ? p[i].z : p[i].w;
                    o[i][0] = fmaf(pi, vb.x, o[i][0]);
                    o[i][1] = fmaf(pi, vb.y, o[i][1]);
                    o[i][2] = fmaf(pi, vb.z, o[i][2]);
                    o[i][3] = fmaf(pi, vb.w, o[i][3]);
                }
            }
        }
    }

    // Epilogue: X[b, q, h*64 + d] = O / l
    #pragma unroll
    for (int i = 0; i < 8; i++) {
        const int qr = (i < 4) ? (ty*4 + i) : (64 + ty*4 + i - 4);
        const float inv = 1.0f / l_i[i];
        float4 outv = make_float4(o[i][0]*inv, o[i][1]*inv, o[i][2]*inv, o[i][3]*inv);
        *(float4*)&X[(rowbase + q0 + qr) * D_MODEL + hoff + tx*4] = outv;
    }
}

// ---------------------------------------------------------------------------
extern "C" void kernel_launch(void* const* d_in, const int* in_sizes, int n_in,
                              void* d_out, int out_size)
{
    const float* q    = (const float*)d_in[0];
    const float* k    = (const float*)d_in[1];
    const float* v    = (const float*)d_in[2];
    const int*   mask = (const int*)  d_in[3];
    const float* Wq   = (const float*)d_in[4];
    const float* bq   = (const float*)d_in[5];
    const float* Wk   = (const float*)d_in[6];
    const float* bk   = (const float*)d_in[7];
    const float* Wv   = (const float*)d_in[8];
    const float* bv   = (const float*)d_in[9];
    const float* Wo   = (const float*)d_in[10];
    const float* bo   = (const float*)d_in[11];
    float* out = (float*)d_out;

    float *Qp, *Kp, *Vp, *Xa;
    cudaGetSymbolAddress((void**)&Qp, g_Qp);
    cudaGetSymbolAddress((void**)&Kp, g_Kp);
    cudaGetSymbolAddress((void**)&Vp, g_Vp);
    cudaGetSymbolAddress((void**)&Xa, g_Xa);

    const int attn_smem = (2*64*132 + 128*68 + 128*132) * (int)sizeof(float); // 169984 B
    cudaFuncSetAttribute(attn_kernel, cudaFuncAttributeMaxDynamicSharedMemorySize, attn_smem);

    dim3 gblk(256);

    // Fused Q/K/V projections: one launch, 576 blocks (better wave packing)
    GemmArgs qkv;
    qkv.A[0] = q;  qkv.A[1] = k;  qkv.A[2] = v;
    qkv.W[0] = Wq; qkv.W[1] = Wk; qkv.W[2] = Wv;
    qkv.bias[0] = bq; qkv.bias[1] = bk; qkv.bias[2] = bv;
    qkv.C[0] = Qp; qkv.C[1] = Kp; qkv.C[2] = Vp;
    gemm_bias_nt<<<dim3(D_MODEL/128, M_ROWS/128, 3), gblk>>>(qkv, M_ROWS, D_MODEL, D_MODEL);

    attn_kernel<<<dim3(S_LEN/128, N_HEADS, B_SZ), 256, attn_smem>>>(Qp, Kp, Vp, mask, Xa);

    // Output projection
    GemmArgs og;
    og.A[0] = Xa; og.A[1] = Xa; og.A[2] = Xa;
    og.W[0] = Wo; og.W[1] = Wo; og.W[2] = Wo;
    og.bias[0] = bo; og.bias[1] = bo; og.bias[2] = bo;
    og.C[0] = out; og.C[1] = out; og.C[2] = out;
    gemm_bias_nt<<<dim3(D_MODEL/128, M_ROWS/128, 1), gblk>>>(og, M_ROWS, D_MODEL, D_MODEL);
}